// round 16
// baseline (speedup 1.0000x reference)
#include <cuda_runtime.h>
#include <cuda_fp16.h>

#define NN 50000
#define NE 800000
#define HID 128
#define H4  32
#define SLOPE 0.2f
#define FULL 0xffffffffu
#define WTS 68             // Wt smem row stride in 32-bit words (136 halves)
#define HGAT_BLOCKS 782    // ceil(NN/64)
#define HIST_BLOCKS 6250   // NE/128
#define SCAN_BLK 1024
#define NSCAN 49           // ceil(NN/SCAN_BLK)

// ---------------- scratch ----------------
__device__ uint2 g_xp[NN * H4];      // GEMM output, fp16 row-major [node][128]
__device__ uint2 g_curh[NN * H4];    // current activation, fp16
__device__ unsigned g_wh[4 * HID * HID / 2];  // 3x GCN W + W_gat, transposed fp16 [n][k]
__device__ float g_ssrc[NN];
__device__ float g_sdst[NN];
__device__ float g_dinv[NN];
__device__ int   g_cnt[NN];
__device__ int   g_rowptr[NN + 1];
__device__ int   g_cursor[NN];
__device__ int   g_blksum[64];
__device__ int2  g_edge[NE];         // (src, weight-bits) -> (src, coeff-bits) after gcn0

// ---------------- fp16 pack/unpack ----------------
__device__ __forceinline__ uint2 pack_h4(float4 o) {
    __half2 h0 = __floats2half2_rn(o.x, o.y);
    __half2 h1 = __floats2half2_rn(o.z, o.w);
    uint2 v;
    v.x = *reinterpret_cast<unsigned int*>(&h0);
    v.y = *reinterpret_cast<unsigned int*>(&h1);
    return v;
}
__device__ __forceinline__ float4 unpack_h4(uint2 v) {
    __half2 h0 = *reinterpret_cast<__half2*>(&v.x);
    __half2 h1 = *reinterpret_cast<__half2*>(&v.y);
    float2 f0 = __half22float2(h0);
    float2 f1 = __half22float2(h1);
    return make_float4(f0.x, f0.y, f1.x, f1.y);
}
__device__ __forceinline__ unsigned cvt_f2_h2(float2 f) {
    __half2 h = __floats2half2_rn(f.x, f.y);
    return *reinterpret_cast<unsigned*>(&h);
}

// ============ convert 4 weight matrices to transposed fp16 ============
__global__ void k_cvtW(const float* __restrict__ Wgcn, const float* __restrict__ Wgat) {
    int m = blockIdx.x;
    const float* Wm = (m < 3) ? (Wgcn + m * HID * HID) : Wgat;
    __half* dst = reinterpret_cast<__half*>(g_wh) + m * HID * HID;
    for (int i = threadIdx.x; i < HID * HID; i += blockDim.x) {
        int k = i >> 7, n = i & 127;
        dst[n * HID + k] = __float2half(Wm[i]);
    }
}

// ================= tensor-core GEMM core (validated mapping) ===========
__device__ __forceinline__ void mma_tile(
    const unsigned* __restrict__ A32, const unsigned* __restrict__ Wt_s,
    int r0c, int r1c, int g, int tg, float* acc) {
#pragma unroll
    for (int i = 0; i < 64; i++) acc[i] = 0.f;
#pragma unroll
    for (int ks = 0; ks < 8; ks++) {
        unsigned a0 = __ldg(A32 + r0c * 64 + ks * 8 + tg);
        unsigned a1 = __ldg(A32 + r1c * 64 + ks * 8 + tg);
        unsigned a2 = __ldg(A32 + r0c * 64 + ks * 8 + tg + 4);
        unsigned a3 = __ldg(A32 + r1c * 64 + ks * 8 + tg + 4);
#pragma unroll
        for (int nt = 0; nt < 16; nt++) {
            unsigned b0 = Wt_s[(nt * 8 + g) * WTS + ks * 8 + tg];
            unsigned b1 = Wt_s[(nt * 8 + g) * WTS + ks * 8 + tg + 4];
            asm volatile(
                "mma.sync.aligned.m16n8k16.row.col.f32.f16.f16.f32 "
                "{%0,%1,%2,%3}, {%4,%5,%6,%7}, {%8,%9}, {%0,%1,%2,%3};"
                : "+f"(acc[nt * 4 + 0]), "+f"(acc[nt * 4 + 1]),
                  "+f"(acc[nt * 4 + 2]), "+f"(acc[nt * 4 + 3])
                : "r"(a0), "r"(a1), "r"(a2), "r"(a3), "r"(b0), "r"(b1));
        }
    }
}
// fp32-input variant: converts x fragments inline (same fragment mapping:
// a-reg word ks*8+tg covers halves k = 16ks+2tg, 16ks+2tg+1)
__device__ __forceinline__ void mma_tile_f32(
    const float2* __restrict__ A2, const unsigned* __restrict__ Wt_s,
    int r0c, int r1c, int g, int tg, float* acc) {
#pragma unroll
    for (int i = 0; i < 64; i++) acc[i] = 0.f;
#pragma unroll
    for (int ks = 0; ks < 8; ks++) {
        unsigned a0 = cvt_f2_h2(__ldg(A2 + r0c * 64 + ks * 8 + tg));
        unsigned a1 = cvt_f2_h2(__ldg(A2 + r1c * 64 + ks * 8 + tg));
        unsigned a2 = cvt_f2_h2(__ldg(A2 + r0c * 64 + ks * 8 + tg + 4));
        unsigned a3 = cvt_f2_h2(__ldg(A2 + r1c * 64 + ks * 8 + tg + 4));
#pragma unroll
        for (int nt = 0; nt < 16; nt++) {
            unsigned b0 = Wt_s[(nt * 8 + g) * WTS + ks * 8 + tg];
            unsigned b1 = Wt_s[(nt * 8 + g) * WTS + ks * 8 + tg + 4];
            asm volatile(
                "mma.sync.aligned.m16n8k16.row.col.f32.f16.f16.f32 "
                "{%0,%1,%2,%3}, {%4,%5,%6,%7}, {%8,%9}, {%0,%1,%2,%3};"
                : "+f"(acc[nt * 4 + 0]), "+f"(acc[nt * 4 + 1]),
                  "+f"(acc[nt * 4 + 2]), "+f"(acc[nt * 4 + 3])
                : "r"(a0), "r"(a1), "r"(a2), "r"(a3), "r"(b0), "r"(b1));
        }
    }
}
__device__ __forceinline__ void store_tile(float* acc, int r0, int r1, int tg) {
    unsigned* xp32 = reinterpret_cast<unsigned*>(g_xp);
#pragma unroll
    for (int nt = 0; nt < 16; nt++) {
        int col = nt * 8 + tg * 2;
        __half2 h01 = __floats2half2_rn(acc[nt * 4 + 0], acc[nt * 4 + 1]);
        __half2 h23 = __floats2half2_rn(acc[nt * 4 + 2], acc[nt * 4 + 3]);
        if (r0 < NN) xp32[r0 * 64 + col / 2] = *reinterpret_cast<unsigned*>(&h01);
        if (r1 < NN) xp32[r1 * 64 + col / 2] = *reinterpret_cast<unsigned*>(&h23);
    }
}

// ====== fused: GAT tensor-core GEMM (fp32 x inline cvt) ∥ degree histogram ==
__global__ void __launch_bounds__(128)
k_hgat_hist(const float* __restrict__ x,
            const float* __restrict__ a_src, const float* __restrict__ a_dst,
            const int* __restrict__ ei) {
    if (blockIdx.x >= HGAT_BLOCKS) {
        int e = (blockIdx.x - HGAT_BLOCKS) * 128 + threadIdx.x;
        if (e < NE) atomicAdd(&g_cnt[ei[NE + e]], 1);
        return;
    }
    __shared__ unsigned Wt_s[HID * WTS];
    const unsigned* wh = g_wh + 3 * (HID * HID / 2);   // W_gat slot
    for (int i = threadIdx.x; i < HID * 64; i += 128) {
        int n = i >> 6, kk = i & 63;
        Wt_s[n * WTS + kk] = wh[n * 64 + kk];
    }
    __syncthreads();

    int warp = threadIdx.x >> 5;
    int lane = threadIdx.x & 31;
    int g = lane >> 2, tg = lane & 3;
    int rows0 = blockIdx.x * 64 + warp * 16;
    int r0 = rows0 + g, r1 = rows0 + g + 8;
    int r0c = min(r0, NN - 1), r1c = min(r1, NN - 1);

    float acc[64];
    mma_tile_f32(reinterpret_cast<const float2*>(x), Wt_s, r0c, r1c, g, tg, acc);
    store_tile(acc, r0, r1, tg);

    float ps0 = 0.f, pd0 = 0.f, ps1 = 0.f, pd1 = 0.f;
    const float2* as2 = reinterpret_cast<const float2*>(a_src);
    const float2* ad2 = reinterpret_cast<const float2*>(a_dst);
#pragma unroll
    for (int nt = 0; nt < 16; nt++) {
        float2 av = __ldg(as2 + nt * 4 + tg);
        float2 dv = __ldg(ad2 + nt * 4 + tg);
        ps0 += acc[nt * 4 + 0] * av.x + acc[nt * 4 + 1] * av.y;
        pd0 += acc[nt * 4 + 0] * dv.x + acc[nt * 4 + 1] * dv.y;
        ps1 += acc[nt * 4 + 2] * av.x + acc[nt * 4 + 3] * av.y;
        pd1 += acc[nt * 4 + 2] * dv.x + acc[nt * 4 + 3] * dv.y;
    }
    ps0 += __shfl_xor_sync(FULL, ps0, 1); ps0 += __shfl_xor_sync(FULL, ps0, 2);
    pd0 += __shfl_xor_sync(FULL, pd0, 1); pd0 += __shfl_xor_sync(FULL, pd0, 2);
    ps1 += __shfl_xor_sync(FULL, ps1, 1); ps1 += __shfl_xor_sync(FULL, ps1, 2);
    pd1 += __shfl_xor_sync(FULL, pd1, 1); pd1 += __shfl_xor_sync(FULL, pd1, 2);
    if (tg == 0) {
        if (r0 < NN) { g_ssrc[r0] = ps0; g_sdst[r0] = pd0; }
        if (r1 < NN) { g_ssrc[r1] = ps1; g_sdst[r1] = pd1; }
    }
}

// ================= GCN tensor-core GEMM =================
__global__ void __launch_bounds__(128)
k_hgemm(int mat) {
    __shared__ unsigned Wt_s[HID * WTS];
    const unsigned* wh = g_wh + mat * (HID * HID / 2);
    for (int i = threadIdx.x; i < HID * 64; i += 128) {
        int n = i >> 6, kk = i & 63;
        Wt_s[n * WTS + kk] = wh[n * 64 + kk];
    }
    __syncthreads();

    int warp = threadIdx.x >> 5;
    int lane = threadIdx.x & 31;
    int g = lane >> 2, tg = lane & 3;
    int rows0 = blockIdx.x * 64 + warp * 16;
    int r0 = rows0 + g, r1 = rows0 + g + 8;
    int r0c = min(r0, NN - 1), r1c = min(r1, NN - 1);

    float acc[64];
    mma_tile(reinterpret_cast<const unsigned*>(g_curh), Wt_s, r0c, r1c, g, tg, acc);
    store_tile(acc, r0, r1, tg);
}

// ================= hierarchical scan =================
__global__ void k_scan1() {
    __shared__ int sh[SCAN_BLK];
    int t = threadIdx.x;
    int i = blockIdx.x * SCAN_BLK + t;
    int v = (i < NN) ? g_cnt[i] : 0;
    sh[t] = v;
    __syncthreads();
    for (int o = 1; o < SCAN_BLK; o <<= 1) {
        int add = (t >= o) ? sh[t - o] : 0;
        __syncthreads();
        sh[t] += add;
        __syncthreads();
    }
    if (i < NN) g_rowptr[i] = sh[t] - v;            // local exclusive
    if (t == SCAN_BLK - 1) g_blksum[blockIdx.x] = sh[t];
}
// scan of 49 block sums done redundantly per block (49 adds in smem), then add.
__global__ void k_scan3() {
    __shared__ int off[NSCAN];
    int t = threadIdx.x;
    if (t == 0) {
        int run = 0;
        for (int b = 0; b < NSCAN; b++) {   // 49 serial adds, L1-hot
            off[b] = run;
            run += g_blksum[b];
        }
    }
    __syncthreads();
    int i = blockIdx.x * blockDim.x + t;
    if (i < NN) {
        int r = g_rowptr[i] + off[i >> 10];
        g_rowptr[i] = r;
        g_cursor[i] = r;
    }
    if (i == 0) g_rowptr[NN] = NE;
}

__global__ void k_place(const int* __restrict__ ei, const float* __restrict__ w) {
    int e = blockIdx.x * blockDim.x + threadIdx.x;
    if (e >= NE) return;
    int d = ei[NE + e];
    int pos = atomicAdd(&g_cursor[d], 1);
    g_edge[pos] = make_int2(ei[e], __float_as_int(w[e]));
}

// ========= GAT gather: 100%-occupancy (<=32 regs), dual-unrolled ==========
__global__ void __launch_bounds__(256, 8)
k_gat(const float* __restrict__ b_gat, float* __restrict__ out) {
    int gw = (blockIdx.x * blockDim.x + threadIdx.x) >> 5;
    int lane = threadIdx.x & 31;
    if (gw >= NN) return;
    int off = g_rowptr[gw], end = g_rowptr[gw + 1];
    float sdst_d = g_sdst[gw];
    float el = g_ssrc[gw] + sdst_d;
    el = el > 0.f ? el : SLOPE * el;
    float p0 = __expf(el);

    float4 xd = unpack_h4(g_xp[gw * H4 + lane]);
    float4 a0 = make_float4(p0 * xd.x, p0 * xd.y, p0 * xd.z, p0 * xd.w);
    float4 a1 = make_float4(0.f, 0.f, 0.f, 0.f);
    float psum = (lane == 0) ? p0 : 0.0f;
    float wsum = (lane == 0) ? 1.0f : 0.0f;

    for (int base = off; base < end; base += 32) {
        int e = base + lane;
        float p = 0.f;
        int s = 0;
        if (e < end) {
            int2 ed = g_edge[e];
            s = ed.x;
            float sc = g_ssrc[s] + sdst_d;
            sc = sc > 0.f ? sc : SLOPE * sc;
            p = __expf(sc);
            wsum += __int_as_float(ed.y);
        }
        psum += p;
        int cnt = min(32, end - base);
        int j = 0;
        for (; j + 2 <= cnt; j += 2) {
            float pj0 = __shfl_sync(FULL, p, j);
            int   sj0 = __shfl_sync(FULL, s, j);
            float pj1 = __shfl_sync(FULL, p, j + 1);
            int   sj1 = __shfl_sync(FULL, s, j + 1);
            float4 x0 = unpack_h4(g_xp[sj0 * H4 + lane]);
            float4 x1 = unpack_h4(g_xp[sj1 * H4 + lane]);
            a0.x += pj0 * x0.x; a0.y += pj0 * x0.y;
            a0.z += pj0 * x0.z; a0.w += pj0 * x0.w;
            a1.x += pj1 * x1.x; a1.y += pj1 * x1.y;
            a1.z += pj1 * x1.z; a1.w += pj1 * x1.w;
        }
        if (j < cnt) {
            float pj = __shfl_sync(FULL, p, j);
            int   sj = __shfl_sync(FULL, s, j);
            float4 xs = unpack_h4(g_xp[sj * H4 + lane]);
            a0.x += pj * xs.x; a0.y += pj * xs.y;
            a0.z += pj * xs.z; a0.w += pj * xs.w;
        }
    }
    float4 acc = make_float4(a0.x + a1.x, a0.y + a1.y, a0.z + a1.z, a0.w + a1.w);
    for (int o = 16; o; o >>= 1) {
        psum += __shfl_xor_sync(FULL, psum, o);
        wsum += __shfl_xor_sync(FULL, wsum, o);
    }
    if (lane == 0) g_dinv[gw] = rsqrtf(wsum);

    float inv = 1.0f / psum;
    float4 b = __ldg(reinterpret_cast<const float4*>(b_gat) + lane);
    float4 h = make_float4(acc.x * inv + b.x, acc.y * inv + b.y,
                           acc.z * inv + b.z, acc.w * inv + b.w);
    g_curh[gw * H4 + lane] = pack_h4(h);
    reinterpret_cast<float4*>(out)[gw * H4 + lane] = h;
}

// ====== GCN gather: 100%-occupancy, dual-unrolled ======
template <bool FIRST, bool LAST>
__global__ void __launch_bounds__(256, 8)
k_gcn(const float* __restrict__ b_gcn, float* __restrict__ out) {
    int gw = (blockIdx.x * blockDim.x + threadIdx.x) >> 5;
    int lane = threadIdx.x & 31;
    if (gw >= NN) return;
    int off = g_rowptr[gw], end = g_rowptr[gw + 1];
    float dv = g_dinv[gw];
    float cs = dv * dv;
    float4 zd = unpack_h4(g_xp[gw * H4 + lane]);
    float4 a0 = make_float4(cs * zd.x, cs * zd.y, cs * zd.z, cs * zd.w);
    float4 a1 = make_float4(0.f, 0.f, 0.f, 0.f);
    for (int base = off; base < end; base += 32) {
        int e = base + lane;
        float c = 0.f;
        int s = 0;
        if (e < end) {
            int2 ed = g_edge[e];
            s = ed.x;
            if (FIRST) {
                c = g_dinv[s] * __int_as_float(ed.y) * dv;
                g_edge[e].y = __float_as_int(c);
            } else {
                c = __int_as_float(ed.y);
            }
        }
        int cnt = min(32, end - base);
        int j = 0;
        for (; j + 2 <= cnt; j += 2) {
            float cj0 = __shfl_sync(FULL, c, j);
            int   sj0 = __shfl_sync(FULL, s, j);
            float cj1 = __shfl_sync(FULL, c, j + 1);
            int   sj1 = __shfl_sync(FULL, s, j + 1);
            float4 z0 = unpack_h4(g_xp[sj0 * H4 + lane]);
            float4 z1 = unpack_h4(g_xp[sj1 * H4 + lane]);
            a0.x += cj0 * z0.x; a0.y += cj0 * z0.y;
            a0.z += cj0 * z0.z; a0.w += cj0 * z0.w;
            a1.x += cj1 * z1.x; a1.y += cj1 * z1.y;
            a1.z += cj1 * z1.z; a1.w += cj1 * z1.w;
        }
        if (j < cnt) {
            float cj = __shfl_sync(FULL, c, j);
            int   sj = __shfl_sync(FULL, s, j);
            float4 zs = unpack_h4(g_xp[sj * H4 + lane]);
            a0.x += cj * zs.x; a0.y += cj * zs.y;
            a0.z += cj * zs.z; a0.w += cj * zs.w;
        }
    }
    float4 acc = make_float4(a0.x + a1.x, a0.y + a1.y, a0.z + a1.z, a0.w + a1.w);
    float4 b = __ldg(reinterpret_cast<const float4*>(b_gcn) + lane);
    float4 z = make_float4(fmaxf(acc.x + b.x, 0.f), fmaxf(acc.y + b.y, 0.f),
                           fmaxf(acc.z + b.z, 0.f), fmaxf(acc.w + b.w, 0.f));
    if (!LAST) g_curh[gw * H4 + lane] = pack_h4(z);
    float4* o4 = reinterpret_cast<float4*>(out) + gw * H4 + lane;
    float4 o = *o4;
    o.x = fmaxf(o.x, z.x); o.y = fmaxf(o.y, z.y);
    o.z = fmaxf(o.z, z.z); o.w = fmaxf(o.w, z.w);
    *o4 = o;
}

extern "C" void kernel_launch(void* const* d_in, const int* in_sizes, int n_in,
                              void* d_out, int out_size) {
    const float* x     = (const float*)d_in[0];
    const int*   ei    = (const int*)  d_in[1];
    const float* emask = (const float*)d_in[2];
    const float* W_gat = (const float*)d_in[3];
    const float* a_src = (const float*)d_in[4];
    const float* a_dst = (const float*)d_in[5];
    const float* b_gat = (const float*)d_in[6];
    const float* W_gcn = (const float*)d_in[7];
    const float* b_gcn = (const float*)d_in[8];
    float* out = (float*)d_out;

    const int edgeBlk  = (NE + 255) / 256;
    const int nwarpBlk = (NN * 32 + 255) / 256;
    const int hgemmBlk = (NN + 63) / 64;
    const int nodeBlk  = (NN + 255) / 256;

    void* cnt_ptr = nullptr;
    cudaGetSymbolAddress(&cnt_ptr, g_cnt);
    cudaMemsetAsync(cnt_ptr, 0, NN * sizeof(int));

    // weight conversion, then (GAT tensor-core GEMM w/ inline x cvt ∥ histogram)
    k_cvtW<<<4, 1024>>>(W_gcn, W_gat);
    k_hgat_hist<<<HGAT_BLOCKS + HIST_BLOCKS, 128>>>(x, a_src, a_dst, ei);

    // hierarchical scan (scan2 folded into scan3)
    k_scan1<<<NSCAN, SCAN_BLK>>>();
    k_scan3<<<nodeBlk, 256>>>();
    k_place<<<edgeBlk, 256>>>(ei, emask);

    // GAT aggregate
    k_gat<<<nwarpBlk, 256>>>(b_gat, out);

    // 3x GCN (tensor-core GEMM) + JK max
    k_hgemm<<<hgemmBlk, 128>>>(0);
    k_gcn<true, false><<<nwarpBlk, 256>>>(b_gcn + 0 * HID, out);
    k_hgemm<<<hgemmBlk, 128>>>(1);
    k_gcn<false, false><<<nwarpBlk, 256>>>(b_gcn + 1 * HID, out);
    k_hgemm<<<hgemmBlk, 128>>>(2);
    k_gcn<false, true><<<nwarpBlk, 256>>>(b_gcn + 2 * HID, out);
}

// round 17
// speedup vs baseline: 1.4001x; 1.4001x over previous
#include <cuda_runtime.h>
#include <cuda_fp16.h>

#define NN 50000
#define NE 800000
#define HID 128
#define H4  32
#define SLOPE 0.2f
#define FULL 0xffffffffu
#define WTS 68             // Wt smem row stride in 32-bit words (136 halves)
#define HGAT_BLOCKS 782    // ceil(NN/64)
#define HIST_BLOCKS 6250   // NE/128
#define SCAN_BLK 1024
#define NSCAN 49           // ceil(NN/SCAN_BLK)

// ---------------- scratch ----------------
__device__ uint2 g_xp[NN * H4];      // GEMM output, fp16 row-major [node][128]
__device__ uint2 g_curh[NN * H4];    // current activation, fp16
__device__ uint2 g_xh[NN * H4];      // input x, fp16
__device__ unsigned g_wh[4 * HID * HID / 2];  // 3x GCN W + W_gat, transposed fp16 [n][k]
__device__ float g_ssrc[NN];
__device__ float g_sdst[NN];
__device__ float g_dinv[NN];
__device__ int   g_cnt[NN];
__device__ int   g_rowptr[NN + 1];
__device__ int   g_cursor[NN];
__device__ int   g_blksum[64];
__device__ int2  g_edge[NE];         // (src, weight-bits) -> (src, coeff-bits) after gcn0

// ---------------- fp16 pack/unpack ----------------
__device__ __forceinline__ uint2 pack_h4(float4 o) {
    __half2 h0 = __floats2half2_rn(o.x, o.y);
    __half2 h1 = __floats2half2_rn(o.z, o.w);
    uint2 v;
    v.x = *reinterpret_cast<unsigned int*>(&h0);
    v.y = *reinterpret_cast<unsigned int*>(&h1);
    return v;
}
__device__ __forceinline__ float4 unpack_h4(uint2 v) {
    __half2 h0 = *reinterpret_cast<__half2*>(&v.x);
    __half2 h1 = *reinterpret_cast<__half2*>(&v.y);
    float2 f0 = __half22float2(h0);
    float2 f1 = __half22float2(h1);
    return make_float4(f0.x, f0.y, f1.x, f1.y);
}

// ============ convert inputs to fp16 ============
__global__ void k_cvtX(const float* __restrict__ x) {
    int i = blockIdx.x * blockDim.x + threadIdx.x;
    if (i < NN * H4)
        g_xh[i] = pack_h4(reinterpret_cast<const float4*>(x)[i]);
}
__global__ void k_cvtW(const float* __restrict__ Wgcn, const float* __restrict__ Wgat) {
    int m = blockIdx.x;
    const float* Wm = (m < 3) ? (Wgcn + m * HID * HID) : Wgat;
    __half* dst = reinterpret_cast<__half*>(g_wh) + m * HID * HID;
    for (int i = threadIdx.x; i < HID * HID; i += blockDim.x) {
        int k = i >> 7, n = i & 127;
        dst[n * HID + k] = __float2half(Wm[i]);
    }
}

// ================= tensor-core GEMM core (validated mapping) ===========
__device__ __forceinline__ void mma_tile(
    const unsigned* __restrict__ A32, const unsigned* __restrict__ Wt_s,
    int r0c, int r1c, int g, int tg, float* acc) {
#pragma unroll
    for (int i = 0; i < 64; i++) acc[i] = 0.f;
#pragma unroll
    for (int ks = 0; ks < 8; ks++) {
        unsigned a0 = __ldg(A32 + r0c * 64 + ks * 8 + tg);
        unsigned a1 = __ldg(A32 + r1c * 64 + ks * 8 + tg);
        unsigned a2 = __ldg(A32 + r0c * 64 + ks * 8 + tg + 4);
        unsigned a3 = __ldg(A32 + r1c * 64 + ks * 8 + tg + 4);
#pragma unroll
        for (int nt = 0; nt < 16; nt++) {
            unsigned b0 = Wt_s[(nt * 8 + g) * WTS + ks * 8 + tg];
            unsigned b1 = Wt_s[(nt * 8 + g) * WTS + ks * 8 + tg + 4];
            asm volatile(
                "mma.sync.aligned.m16n8k16.row.col.f32.f16.f16.f32 "
                "{%0,%1,%2,%3}, {%4,%5,%6,%7}, {%8,%9}, {%0,%1,%2,%3};"
                : "+f"(acc[nt * 4 + 0]), "+f"(acc[nt * 4 + 1]),
                  "+f"(acc[nt * 4 + 2]), "+f"(acc[nt * 4 + 3])
                : "r"(a0), "r"(a1), "r"(a2), "r"(a3), "r"(b0), "r"(b1));
        }
    }
}
__device__ __forceinline__ void store_tile(float* acc, int r0, int r1, int tg) {
    unsigned* xp32 = reinterpret_cast<unsigned*>(g_xp);
#pragma unroll
    for (int nt = 0; nt < 16; nt++) {
        int col = nt * 8 + tg * 2;
        __half2 h01 = __floats2half2_rn(acc[nt * 4 + 0], acc[nt * 4 + 1]);
        __half2 h23 = __floats2half2_rn(acc[nt * 4 + 2], acc[nt * 4 + 3]);
        if (r0 < NN) xp32[r0 * 64 + col / 2] = *reinterpret_cast<unsigned*>(&h01);
        if (r1 < NN) xp32[r1 * 64 + col / 2] = *reinterpret_cast<unsigned*>(&h23);
    }
}

// ====== fused: GAT tensor-core GEMM (+score epilogue)  ∥  degree histogram ==
__global__ void __launch_bounds__(128)
k_hgat_hist(const float* __restrict__ a_src, const float* __restrict__ a_dst,
            const int* __restrict__ ei) {
    if (blockIdx.x >= HGAT_BLOCKS) {
        int e = (blockIdx.x - HGAT_BLOCKS) * 128 + threadIdx.x;
        if (e < NE) atomicAdd(&g_cnt[ei[NE + e]], 1);
        return;
    }
    __shared__ unsigned Wt_s[HID * WTS];
    const unsigned* wh = g_wh + 3 * (HID * HID / 2);   // W_gat slot
    for (int i = threadIdx.x; i < HID * 64; i += 128) {
        int n = i >> 6, kk = i & 63;
        Wt_s[n * WTS + kk] = wh[n * 64 + kk];
    }
    __syncthreads();

    int warp = threadIdx.x >> 5;
    int lane = threadIdx.x & 31;
    int g = lane >> 2, tg = lane & 3;
    int rows0 = blockIdx.x * 64 + warp * 16;
    int r0 = rows0 + g, r1 = rows0 + g + 8;
    int r0c = min(r0, NN - 1), r1c = min(r1, NN - 1);

    float acc[64];
    mma_tile(reinterpret_cast<const unsigned*>(g_xh), Wt_s, r0c, r1c, g, tg, acc);
    store_tile(acc, r0, r1, tg);

    float ps0 = 0.f, pd0 = 0.f, ps1 = 0.f, pd1 = 0.f;
    const float2* as2 = reinterpret_cast<const float2*>(a_src);
    const float2* ad2 = reinterpret_cast<const float2*>(a_dst);
#pragma unroll
    for (int nt = 0; nt < 16; nt++) {
        float2 av = __ldg(as2 + nt * 4 + tg);
        float2 dv = __ldg(ad2 + nt * 4 + tg);
        ps0 += acc[nt * 4 + 0] * av.x + acc[nt * 4 + 1] * av.y;
        pd0 += acc[nt * 4 + 0] * dv.x + acc[nt * 4 + 1] * dv.y;
        ps1 += acc[nt * 4 + 2] * av.x + acc[nt * 4 + 3] * av.y;
        pd1 += acc[nt * 4 + 2] * dv.x + acc[nt * 4 + 3] * dv.y;
    }
    ps0 += __shfl_xor_sync(FULL, ps0, 1); ps0 += __shfl_xor_sync(FULL, ps0, 2);
    pd0 += __shfl_xor_sync(FULL, pd0, 1); pd0 += __shfl_xor_sync(FULL, pd0, 2);
    ps1 += __shfl_xor_sync(FULL, ps1, 1); ps1 += __shfl_xor_sync(FULL, ps1, 2);
    pd1 += __shfl_xor_sync(FULL, pd1, 1); pd1 += __shfl_xor_sync(FULL, pd1, 2);
    if (tg == 0) {
        if (r0 < NN) { g_ssrc[r0] = ps0; g_sdst[r0] = pd0; }
        if (r1 < NN) { g_ssrc[r1] = ps1; g_sdst[r1] = pd1; }
    }
}

// ================= GCN tensor-core GEMM =================
__global__ void __launch_bounds__(128)
k_hgemm(int mat) {
    __shared__ unsigned Wt_s[HID * WTS];
    const unsigned* wh = g_wh + mat * (HID * HID / 2);
    for (int i = threadIdx.x; i < HID * 64; i += 128) {
        int n = i >> 6, kk = i & 63;
        Wt_s[n * WTS + kk] = wh[n * 64 + kk];
    }
    __syncthreads();

    int warp = threadIdx.x >> 5;
    int lane = threadIdx.x & 31;
    int g = lane >> 2, tg = lane & 3;
    int rows0 = blockIdx.x * 64 + warp * 16;
    int r0 = rows0 + g, r1 = rows0 + g + 8;
    int r0c = min(r0, NN - 1), r1c = min(r1, NN - 1);

    float acc[64];
    mma_tile(reinterpret_cast<const unsigned*>(g_curh), Wt_s, r0c, r1c, g, tg, acc);
    store_tile(acc, r0, r1, tg);
}

// ================= hierarchical scan (coalesced, multi-block) ==============
__global__ void k_scan1() {
    __shared__ int sh[SCAN_BLK];
    int t = threadIdx.x;
    int i = blockIdx.x * SCAN_BLK + t;
    int v = (i < NN) ? g_cnt[i] : 0;
    sh[t] = v;
    __syncthreads();
    for (int o = 1; o < SCAN_BLK; o <<= 1) {
        int add = (t >= o) ? sh[t - o] : 0;
        __syncthreads();
        sh[t] += add;
        __syncthreads();
    }
    if (i < NN) g_rowptr[i] = sh[t] - v;            // local exclusive
    if (t == SCAN_BLK - 1) g_blksum[blockIdx.x] = sh[t];
}
__global__ void k_scan2() {
    __shared__ int sh[64];
    int t = threadIdx.x;
    int v = (t < NSCAN) ? g_blksum[t] : 0;
    sh[t] = v;
    __syncthreads();
    for (int o = 1; o < 64; o <<= 1) {
        int add = (t >= o) ? sh[t - o] : 0;
        __syncthreads();
        sh[t] += add;
        __syncthreads();
    }
    if (t < NSCAN) g_blksum[t] = sh[t] - v;         // exclusive block offsets
    if (t == 0) g_rowptr[NN] = NE;                  // total is a known constant
}
__global__ void k_scan3() {
    int i = blockIdx.x * blockDim.x + threadIdx.x;
    if (i < NN) {
        int r = g_rowptr[i] + g_blksum[i >> 10];
        g_rowptr[i] = r;
        g_cursor[i] = r;
    }
}

__global__ void k_place(const int* __restrict__ ei, const float* __restrict__ w) {
    int e = blockIdx.x * blockDim.x + threadIdx.x;
    if (e >= NE) return;
    int d = ei[NE + e];
    int pos = atomicAdd(&g_cursor[d], 1);
    g_edge[pos] = make_int2(ei[e], __float_as_int(w[e]));
}

// ========= GAT gather: 100%-occupancy (<=32 regs), dual-unrolled ==========
__global__ void __launch_bounds__(256, 8)
k_gat(const float* __restrict__ b_gat, float* __restrict__ out) {
    int gw = (blockIdx.x * blockDim.x + threadIdx.x) >> 5;
    int lane = threadIdx.x & 31;
    if (gw >= NN) return;
    int off = g_rowptr[gw], end = g_rowptr[gw + 1];
    float sdst_d = g_sdst[gw];
    float el = g_ssrc[gw] + sdst_d;
    el = el > 0.f ? el : SLOPE * el;
    float p0 = __expf(el);

    float4 xd = unpack_h4(g_xp[gw * H4 + lane]);
    float4 a0 = make_float4(p0 * xd.x, p0 * xd.y, p0 * xd.z, p0 * xd.w);
    float4 a1 = make_float4(0.f, 0.f, 0.f, 0.f);
    float psum = (lane == 0) ? p0 : 0.0f;
    float wsum = (lane == 0) ? 1.0f : 0.0f;

    for (int base = off; base < end; base += 32) {
        int e = base + lane;
        float p = 0.f;
        int s = 0;
        if (e < end) {
            int2 ed = g_edge[e];
            s = ed.x;
            float sc = g_ssrc[s] + sdst_d;
            sc = sc > 0.f ? sc : SLOPE * sc;
            p = __expf(sc);
            wsum += __int_as_float(ed.y);
        }
        psum += p;
        int cnt = min(32, end - base);
        int j = 0;
        for (; j + 2 <= cnt; j += 2) {
            float pj0 = __shfl_sync(FULL, p, j);
            int   sj0 = __shfl_sync(FULL, s, j);
            float pj1 = __shfl_sync(FULL, p, j + 1);
            int   sj1 = __shfl_sync(FULL, s, j + 1);
            float4 x0 = unpack_h4(g_xp[sj0 * H4 + lane]);
            float4 x1 = unpack_h4(g_xp[sj1 * H4 + lane]);
            a0.x += pj0 * x0.x; a0.y += pj0 * x0.y;
            a0.z += pj0 * x0.z; a0.w += pj0 * x0.w;
            a1.x += pj1 * x1.x; a1.y += pj1 * x1.y;
            a1.z += pj1 * x1.z; a1.w += pj1 * x1.w;
        }
        if (j < cnt) {
            float pj = __shfl_sync(FULL, p, j);
            int   sj = __shfl_sync(FULL, s, j);
            float4 xs = unpack_h4(g_xp[sj * H4 + lane]);
            a0.x += pj * xs.x; a0.y += pj * xs.y;
            a0.z += pj * xs.z; a0.w += pj * xs.w;
        }
    }
    float4 acc = make_float4(a0.x + a1.x, a0.y + a1.y, a0.z + a1.z, a0.w + a1.w);
    for (int o = 16; o; o >>= 1) {
        psum += __shfl_xor_sync(FULL, psum, o);
        wsum += __shfl_xor_sync(FULL, wsum, o);
    }
    if (lane == 0) g_dinv[gw] = rsqrtf(wsum);

    float inv = 1.0f / psum;
    float4 b = __ldg(reinterpret_cast<const float4*>(b_gat) + lane);
    float4 h = make_float4(acc.x * inv + b.x, acc.y * inv + b.y,
                           acc.z * inv + b.z, acc.w * inv + b.w);
    g_curh[gw * H4 + lane] = pack_h4(h);
    reinterpret_cast<float4*>(out)[gw * H4 + lane] = h;
}

// ====== GCN gather: 100%-occupancy, dual-unrolled; LAST skips dead store ===
template <bool FIRST, bool LAST>
__global__ void __launch_bounds__(256, 8)
k_gcn(const float* __restrict__ b_gcn, float* __restrict__ out) {
    int gw = (blockIdx.x * blockDim.x + threadIdx.x) >> 5;
    int lane = threadIdx.x & 31;
    if (gw >= NN) return;
    int off = g_rowptr[gw], end = g_rowptr[gw + 1];
    float dv = g_dinv[gw];
    float cs = dv * dv;
    float4 zd = unpack_h4(g_xp[gw * H4 + lane]);
    float4 a0 = make_float4(cs * zd.x, cs * zd.y, cs * zd.z, cs * zd.w);
    float4 a1 = make_float4(0.f, 0.f, 0.f, 0.f);
    for (int base = off; base < end; base += 32) {
        int e = base + lane;
        float c = 0.f;
        int s = 0;
        if (e < end) {
            int2 ed = g_edge[e];
            s = ed.x;
            if (FIRST) {
                c = g_dinv[s] * __int_as_float(ed.y) * dv;
                g_edge[e].y = __float_as_int(c);
            } else {
                c = __int_as_float(ed.y);
            }
        }
        int cnt = min(32, end - base);
        int j = 0;
        for (; j + 2 <= cnt; j += 2) {
            float cj0 = __shfl_sync(FULL, c, j);
            int   sj0 = __shfl_sync(FULL, s, j);
            float cj1 = __shfl_sync(FULL, c, j + 1);
            int   sj1 = __shfl_sync(FULL, s, j + 1);
            float4 z0 = unpack_h4(g_xp[sj0 * H4 + lane]);
            float4 z1 = unpack_h4(g_xp[sj1 * H4 + lane]);
            a0.x += cj0 * z0.x; a0.y += cj0 * z0.y;
            a0.z += cj0 * z0.z; a0.w += cj0 * z0.w;
            a1.x += cj1 * z1.x; a1.y += cj1 * z1.y;
            a1.z += cj1 * z1.z; a1.w += cj1 * z1.w;
        }
        if (j < cnt) {
            float cj = __shfl_sync(FULL, c, j);
            int   sj = __shfl_sync(FULL, s, j);
            float4 zs = unpack_h4(g_xp[sj * H4 + lane]);
            a0.x += cj * zs.x; a0.y += cj * zs.y;
            a0.z += cj * zs.z; a0.w += cj * zs.w;
        }
    }
    float4 acc = make_float4(a0.x + a1.x, a0.y + a1.y, a0.z + a1.z, a0.w + a1.w);
    float4 b = __ldg(reinterpret_cast<const float4*>(b_gcn) + lane);
    float4 z = make_float4(fmaxf(acc.x + b.x, 0.f), fmaxf(acc.y + b.y, 0.f),
                           fmaxf(acc.z + b.z, 0.f), fmaxf(acc.w + b.w, 0.f));
    if (!LAST) g_curh[gw * H4 + lane] = pack_h4(z);
    float4* o4 = reinterpret_cast<float4*>(out) + gw * H4 + lane;
    float4 o = *o4;
    o.x = fmaxf(o.x, z.x); o.y = fmaxf(o.y, z.y);
    o.z = fmaxf(o.z, z.z); o.w = fmaxf(o.w, z.w);
    *o4 = o;
}

extern "C" void kernel_launch(void* const* d_in, const int* in_sizes, int n_in,
                              void* d_out, int out_size) {
    const float* x     = (const float*)d_in[0];
    const int*   ei    = (const int*)  d_in[1];
    const float* emask = (const float*)d_in[2];
    const float* W_gat = (const float*)d_in[3];
    const float* a_src = (const float*)d_in[4];
    const float* a_dst = (const float*)d_in[5];
    const float* b_gat = (const float*)d_in[6];
    const float* W_gcn = (const float*)d_in[7];
    const float* b_gcn = (const float*)d_in[8];
    float* out = (float*)d_out;

    const int edgeBlk  = (NE + 255) / 256;
    const int nwarpBlk = (NN * 32 + 255) / 256;
    const int hgemmBlk = (NN + 63) / 64;
    const int cvtXBlk  = (NN * H4 + 255) / 256;
    const int nodeBlk  = (NN + 255) / 256;

    void* cnt_ptr = nullptr;
    cudaGetSymbolAddress(&cnt_ptr, g_cnt);
    cudaMemsetAsync(cnt_ptr, 0, NN * sizeof(int));

    // conversions, then (GAT tensor-core GEMM ∥ degree histogram)
    k_cvtW<<<4, 1024>>>(W_gcn, W_gat);
    k_cvtX<<<cvtXBlk, 256>>>(x);
    k_hgat_hist<<<HGAT_BLOCKS + HIST_BLOCKS, 128>>>(a_src, a_dst, ei);

    // hierarchical scan
    k_scan1<<<NSCAN, SCAN_BLK>>>();
    k_scan2<<<1, 64>>>();
    k_scan3<<<nodeBlk, 256>>>();
    k_place<<<edgeBlk, 256>>>(ei, emask);

    // GAT aggregate
    k_gat<<<nwarpBlk, 256>>>(b_gat, out);

    // 3x GCN (tensor-core GEMM) + JK max
    k_hgemm<<<hgemmBlk, 128>>>(0);
    k_gcn<true, false><<<nwarpBlk, 256>>>(b_gcn + 0 * HID, out);
    k_hgemm<<<hgemmBlk, 128>>>(1);
    k_gcn<false, false><<<nwarpBlk, 256>>>(b_gcn + 1 * HID, out);
    k_hgemm<<<hgemmBlk, 128>>>(2);
    k_gcn<false, true><<<nwarpBlk, 256>>>(b_gcn + 2 * HID, out);
}